// round 6
// baseline (speedup 1.0000x reference)
#include <cuda_runtime.h>
#include <stdint.h>

#define BATCH 64
#define T 2048
#define HID 256
#define FAST 64
#define SLOW 256
#define VOCAB 64
#define TLOOP (T - 3)

typedef unsigned long long u64;

__device__ __forceinline__ int warp_incl_scan(int x, int lane) {
    #pragma unroll
    for (int off = 1; off < 32; off <<= 1) {
        int t = __shfl_up_sync(0xffffffffu, x, off);
        if (lane >= off) x += t;
    }
    return x;
}

__global__ void __launch_bounds__(256) fused_kernel(
    const int* __restrict__ seq,
    const float* __restrict__ emb,
    const float* __restrict__ Wg, const float* __restrict__ bg,
    const float* __restrict__ Wd, const float* __restrict__ bd,
    const float* __restrict__ Wq, const float* __restrict__ bq,
    const float* __restrict__ Wo, const float* __restrict__ bo,
    float* __restrict__ out)
{
    __shared__ float s_dem[VOCAB];
    __shared__ int s_rankv[VOCAB];
    __shared__ int s_vid[VOCAB];
    __shared__ unsigned s_am[2];
    __shared__ int s_ccnt[64];
    __shared__ int s_cpre[64];
    __shared__ int s_ha[VOCAB];
    __shared__ int s_ht[VOCAB];
    __shared__ int s_h1[VOCAB];
    __shared__ int s_h2[VOCAB];
    __shared__ int s_c1[VOCAB];
    __shared__ int s_c2[VOCAB];
    __shared__ int s_mrank, s_m;
    __shared__ float s_elv[HID];
    __shared__ float s_q[HID];
    __shared__ float s_ctx[HID];
    __shared__ float s_pv[VOCAB];     // score indexed by vid
    __shared__ float s_w[VOCAB];      // weight indexed by rank
    __shared__ float s_r8[8];
    __shared__ float s_half[256];

    const int b = blockIdx.x;
    const int tid = threadIdx.x;
    const int wid = tid >> 5, lane = tid & 31;
    const int* sb = seq + b * T;

    if (tid < 2) s_am[tid] = 0u;
    if (tid < VOCAB) { s_ha[tid] = 0; s_ht[tid] = 0; }
    if (tid == 0) s_mrank = -1;
    __syncthreads();

    const int lv = sb[T - 1];

    if (tid < 128) {
        // ================= pipeline A: gates / ranks / token histograms ====
        const float bg0 = bg[0];
        const float bd0 = bd[0];
        #pragma unroll
        for (int rr = 0; rr < 16; ++rr) {
            const int row = wid * 16 + rr;
            const float* er = emb + row * HID;
            float ag = 0.f, ad = 0.f;
            #pragma unroll
            for (int k = 0; k < 8; ++k) {
                float e = er[lane + 32 * k];
                ag += e * Wg[lane + 32 * k];
                ad += e * Wd[lane + 32 * k];
            }
            #pragma unroll
            for (int off = 16; off > 0; off >>= 1) {
                ag += __shfl_xor_sync(0xffffffffu, ag, off);
                ad += __shfl_xor_sync(0xffffffffu, ad, off);
            }
            if (lane == 0) {
                s_dem[row] = ad + bd0;
                float x = ag + bg0;
                float ws = 1.f / (1.f + expf(-x));
                if (ws >= 0.4f) atomicOr(&s_am[row >> 5], 1u << (row & 31));
            }
        }
        asm volatile("bar.sync 1, 128;" ::: "memory");

        // ranks by ascending dem (tie: lower vid)
        if (tid < VOCAB) {
            float dv = s_dem[tid];
            int rank = 0;
            #pragma unroll 8
            for (int u = 0; u < VOCAB; ++u) {
                float du = s_dem[u];
                if (du < dv || (du == dv && u < tid)) rank++;
            }
            s_rankv[tid] = rank;
            s_vid[rank] = tid;
        }
        asm volatile("bar.sync 1, 128;" ::: "memory");

        const u64 act = (u64)s_am[0] | ((u64)s_am[1] << 32);

        // pass 1: per-chunk active counts
        #pragma unroll
        for (int it = 0; it < 16; ++it) {
            const int chunk = wid * 16 + it;
            const int t = chunk * 32 + lane;
            bool a = false;
            if (t < TLOOP) a = ((act >> sb[t]) & 1ull) != 0ull;
            unsigned ball = __ballot_sync(0xffffffffu, a);
            if (lane == 0) s_ccnt[chunk] = __popc(ball);
        }
        asm volatile("bar.sync 1, 128;" ::: "memory");

        // chunk prefix scan (warp 0, 2 per lane)
        if (wid == 0) {
            int a0 = s_ccnt[2 * lane], a1 = s_ccnt[2 * lane + 1];
            int s = warp_incl_scan(a0 + a1, lane);
            int excl = s - a0 - a1;
            s_cpre[2 * lane] = excl;
            s_cpre[2 * lane + 1] = excl + a0;
            if (lane == 31) s_m = s;
        }
        asm volatile("bar.sync 1, 128;" ::: "memory");

        const int m = s_m;
        // pass 2: histograms with positional cutoffs
        #pragma unroll
        for (int it = 0; it < 16; ++it) {
            const int chunk = wid * 16 + it;
            const int t = chunk * 32 + lane;
            bool a = false; int rk = 0;
            if (t < TLOOP) {
                int v = sb[t];
                a = ((act >> v) & 1ull) != 0ull;
                rk = s_rankv[v];
            }
            unsigned ball = __ballot_sync(0xffffffffu, a);
            if (a) {
                int yi = s_cpre[chunk] + __popc(ball & ((1u << lane) - 1u)) + 1;
                atomicAdd(&s_ha[rk], 1);
                if (yi >= m - 256 && yi <= m - 1) atomicAdd(&s_ht[rk], 1);
                if (yi == m) s_mrank = rk;
            }
        }
    } else {
        // ================= pipeline B: q matvec + p dots (vid-indexed) =====
        const int j = tid - 128;
        s_elv[j] = emb[lv * HID + j];
        s_elv[j + 128] = emb[lv * HID + j + 128];
        asm volatile("bar.sync 2, 128;" ::: "memory");

        float a0 = bq[j];
        float a1 = bq[j + 128];
        #pragma unroll 8
        for (int h = 0; h < HID; ++h) {
            const float e = s_elv[h];
            const float* row = Wq + h * HID;
            a0 += e * row[j];
            a1 += e * row[j + 128];
        }
        s_q[j] = a0;
        s_q[j + 128] = a1;
        asm volatile("bar.sync 2, 128;" ::: "memory");

        // p[v] = emb[v] . q  (4 warps x 16 vids)
        #pragma unroll
        for (int rr = 0; rr < 16; ++rr) {
            const int v = (wid - 4) * 16 + rr;
            const float* er = emb + v * HID;
            float acc = 0.f;
            #pragma unroll
            for (int k = 0; k < 8; ++k)
                acc += er[lane + 32 * k] * s_q[lane + 32 * k];
            #pragma unroll
            for (int off = 16; off > 0; off >>= 1)
                acc += __shfl_xor_sync(0xffffffffu, acc, off);
            if (lane == 0) s_pv[v] = acc;
        }
    }
    __syncthreads();

    const int m = s_m;
    const int ne = (m > FAST) ? (m - FAST) : 0;
    const int k1 = ne;
    const int k2 = (ne > SLOW) ? (ne - SLOW) : 0;
    const int scnt = (ne < SLOW) ? ne : SLOW;
    const int mrank = s_mrank;

    if (tid < VOCAB) {
        int h1 = s_ha[tid] - (tid == mrank ? 1 : 0);
        s_h1[tid] = h1;
        s_h2[tid] = h1 - s_ht[tid];
    }
    __syncthreads();

    // prefix scans of h1/h2 (warp 0, 2 per lane)
    if (wid == 0) {
        int a1_ = s_h1[2 * lane], b1_ = s_h1[2 * lane + 1];
        int a2_ = s_h2[2 * lane], b2_ = s_h2[2 * lane + 1];
        int s1 = warp_incl_scan(a1_ + b1_, lane);
        int s2 = warp_incl_scan(a2_ + b2_, lane);
        int e1 = s1 - a1_ - b1_;
        int e2 = s2 - a2_ - b2_;
        s_c1[2 * lane] = e1;  s_c1[2 * lane + 1] = e1 + a1_;
        s_c2[2 * lane] = e2;  s_c2[2 * lane + 1] = e2 + a2_;
    }
    __syncthreads();

    // closed-form counts per rank
    int ct = 0;
    float p = 0.f;
    if (tid < VOCAB) {
        const int h1 = s_h1[tid], h2 = s_h2[tid];
        int e1 = k1 - s_c1[tid]; e1 = e1 < 0 ? 0 : e1; e1 = e1 > h1 ? h1 : e1;
        int e2 = k2 - s_c2[tid]; e2 = e2 < 0 ? 0 : e2; e2 = e2 > h2 ? h2 : e2;
        ct = (h1 - e1 + (tid == mrank ? 1 : 0)) + (e1 - e2);
        p = s_pv[s_vid[tid]];
    }

    // softmax over ranks weighted by counts
    float v = (tid < VOCAB && ct > 0) ? p : -3.402823466e38f;
    #pragma unroll
    for (int off = 16; off > 0; off >>= 1)
        v = fmaxf(v, __shfl_xor_sync(0xffffffffu, v, off));
    if (lane == 0) s_r8[wid] = v;
    __syncthreads();
    float mx = fmaxf(s_r8[0], s_r8[1]);
    __syncthreads();

    float e = (tid < VOCAB && ct > 0) ? (float)ct * expf(p - mx) : 0.f;
    float sm = e;
    #pragma unroll
    for (int off = 16; off > 0; off >>= 1)
        sm += __shfl_xor_sync(0xffffffffu, sm, off);
    if (lane == 0) s_r8[wid] = sm;
    __syncthreads();
    const float tot = s_r8[0] + s_r8[1];
    const float inv = (tot > 0.f) ? (1.f / tot) : 0.f;
    if (tid < VOCAB) s_w[tid] = e * inv;
    __syncthreads();

    // ctx[h] = sum_r w[r] * emb[vid[r]][h]
    {
        float c = 0.f;
        #pragma unroll 8
        for (int r = 0; r < VOCAB; ++r)
            c += s_w[r] * emb[s_vid[r] * HID + tid];
        s_ctx[tid] = c;
    }
    __syncthreads();

    // logits[j] = bo[j] + ctx . Wo[:,j]
    {
        const int j = tid & 63;
        const int qd = tid >> 6;
        float acc = 0.f;
        #pragma unroll 8
        for (int k = 0; k < 64; ++k) {
            const int h = qd * 64 + k;
            acc += s_ctx[h] * Wo[h * VOCAB + j];
        }
        s_half[tid] = acc;
    }
    __syncthreads();
    if (tid < VOCAB)
        out[b * VOCAB + tid] = bo[tid] + s_half[tid] + s_half[tid + 64] +
                               s_half[tid + 128] + s_half[tid + 192];

    for (int j = tid; j < SLOW; j += 256)
        out[BATCH * VOCAB + b * SLOW + j] = (j < scnt) ? 1.f : 0.f;
}

extern "C" void kernel_launch(void* const* d_in, const int* in_sizes, int n_in,
                              void* d_out, int out_size) {
    const int*   seq = (const int*)d_in[0];
    const float* emb = (const float*)d_in[1];
    const float* Wg  = (const float*)d_in[2];
    const float* bg  = (const float*)d_in[3];
    const float* Wd  = (const float*)d_in[4];
    const float* bd  = (const float*)d_in[5];
    const float* Wq  = (const float*)d_in[6];
    const float* bq  = (const float*)d_in[7];
    const float* Wo  = (const float*)d_in[8];
    const float* bo  = (const float*)d_in[9];
    float* out = (float*)d_out;

    fused_kernel<<<BATCH, 256>>>(seq, emb, Wg, bg, Wd, bd, Wq, bq, Wo, bo, out);
}

// round 7
// speedup vs baseline: 1.5668x; 1.5668x over previous
#include <cuda_runtime.h>
#include <stdint.h>

#define BATCH 64
#define T 2048
#define HID 256
#define FAST 64
#define SLOW 256
#define VOCAB 64
#define TLOOP (T - 3)

typedef unsigned long long u64;

__device__ __forceinline__ int warp_incl_scan(int x, int lane) {
    #pragma unroll
    for (int off = 1; off < 32; off <<= 1) {
        int t = __shfl_up_sync(0xffffffffu, x, off);
        if (lane >= off) x += t;
    }
    return x;
}

__global__ void __launch_bounds__(512) fused_kernel(
    const int* __restrict__ seq,
    const float* __restrict__ emb,
    const float* __restrict__ Wg, const float* __restrict__ bg,
    const float* __restrict__ Wd, const float* __restrict__ bd,
    const float* __restrict__ Wq, const float* __restrict__ bq,
    const float* __restrict__ Wo, const float* __restrict__ bo,
    float* __restrict__ out)
{
    __shared__ __align__(16) int s_seq[T];
    __shared__ float s_dem[VOCAB];
    __shared__ int s_rankv[VOCAB];
    __shared__ int s_vid[VOCAB];
    __shared__ unsigned s_am[2];
    __shared__ int s_ccnt[64];
    __shared__ int s_cpre[64];
    __shared__ int s_ha[VOCAB];
    __shared__ int s_ht[VOCAB];
    __shared__ int s_h1[VOCAB];
    __shared__ int s_h2[VOCAB];
    __shared__ int s_c1[VOCAB];
    __shared__ int s_c2[VOCAB];
    __shared__ int s_mrank, s_m;
    __shared__ float s_elv[HID];
    __shared__ float s_q[HID];
    __shared__ float s_ctxp[512];
    __shared__ float s_ctx[HID];
    __shared__ float s_pv[VOCAB];
    __shared__ float s_w[VOCAB];
    __shared__ float s_r8[2];
    __shared__ float s_half[512];

    const int b = blockIdx.x;
    const int tid = threadIdx.x;
    const int wid = tid >> 5, lane = tid & 31;

    // ---- stage seq (one int4 per thread, full-MLP DRAM burst) ----
    reinterpret_cast<int4*>(s_seq)[tid] =
        reinterpret_cast<const int4*>(seq + b * T)[tid];
    if (tid < 2) s_am[tid] = 0u;
    if (tid < VOCAB) { s_ha[tid] = 0; s_ht[tid] = 0; }
    if (tid == 0) s_mrank = -1;
    __syncthreads();

    const int lv = s_seq[T - 1];

    if (tid < 256) {
        // ================= pipeline A =================
        const float bg0 = bg[0];
        const float bd0 = bd[0];
        #pragma unroll
        for (int rr = 0; rr < 8; ++rr) {
            const int row = wid * 8 + rr;
            const float* er = emb + row * HID;
            float ag = 0.f, ad = 0.f;
            #pragma unroll
            for (int k = 0; k < 8; ++k) {
                float e = er[lane + 32 * k];
                ag += e * Wg[lane + 32 * k];
                ad += e * Wd[lane + 32 * k];
            }
            #pragma unroll
            for (int off = 16; off > 0; off >>= 1) {
                ag += __shfl_xor_sync(0xffffffffu, ag, off);
                ad += __shfl_xor_sync(0xffffffffu, ad, off);
            }
            if (lane == 0) {
                s_dem[row] = ad + bd0;
                float x = ag + bg0;
                float ws = 1.f / (1.f + expf(-x));
                if (ws >= 0.4f) atomicOr(&s_am[row >> 5], 1u << (row & 31));
            }
        }
        asm volatile("bar.sync 1, 256;" ::: "memory");

        if (tid < VOCAB) {
            float dv = s_dem[tid];
            int rank = 0;
            #pragma unroll 8
            for (int u = 0; u < VOCAB; ++u) {
                float du = s_dem[u];
                if (du < dv || (du == dv && u < tid)) rank++;
            }
            s_rankv[tid] = rank;
            s_vid[rank] = tid;
        }

        const u64 act = (u64)s_am[0] | ((u64)s_am[1] << 32);

        // pass 1: 8 chunks/warp, tokens+ballots cached in registers
        int toks[8];
        unsigned ball[8];
        bool av[8];
        #pragma unroll
        for (int i = 0; i < 8; ++i) {
            const int chunk = wid * 8 + i;
            const int t = chunk * 32 + lane;
            toks[i] = s_seq[t];
            av[i] = (t < TLOOP) && (((act >> toks[i]) & 1ull) != 0ull);
            ball[i] = __ballot_sync(0xffffffffu, av[i]);
            if (lane == 0) s_ccnt[chunk] = __popc(ball[i]);
        }
        asm volatile("bar.sync 1, 256;" ::: "memory");

        if (wid == 0) {
            int a0 = s_ccnt[2 * lane], a1 = s_ccnt[2 * lane + 1];
            int s = warp_incl_scan(a0 + a1, lane);
            int excl = s - a0 - a1;
            s_cpre[2 * lane] = excl;
            s_cpre[2 * lane + 1] = excl + a0;
            if (lane == 31) s_m = s;
        }
        asm volatile("bar.sync 1, 256;" ::: "memory");

        const int m = s_m;
        // slow_mask output (needs only m): 256 A-threads, one elem each
        {
            const int ne_ = (m > FAST) ? (m - FAST) : 0;
            const int sc_ = (ne_ < SLOW) ? ne_ : SLOW;
            out[BATCH * VOCAB + b * SLOW + tid] = (tid < sc_) ? 1.f : 0.f;
        }
        // pass 2: reuse cached tokens/ballots
        const unsigned lmask = (1u << lane) - 1u;
        #pragma unroll
        for (int i = 0; i < 8; ++i) {
            if (av[i]) {
                const int chunk = wid * 8 + i;
                const int yi = s_cpre[chunk] + __popc(ball[i] & lmask) + 1;
                const int rk = s_rankv[toks[i]];
                atomicAdd(&s_ha[rk], 1);
                if (yi >= m - 256 && yi <= m - 1) atomicAdd(&s_ht[rk], 1);
                if (yi == m) s_mrank = rk;
            }
        }
    } else {
        // ================= pipeline B =================
        const int j = tid - 256;     // 0..255
        s_elv[j] = emb[lv * HID + j];
        asm volatile("bar.sync 2, 256;" ::: "memory");

        float acc = bq[j];
        #pragma unroll 16
        for (int h = 0; h < HID; ++h)
            acc += s_elv[h] * Wq[h * HID + j];
        s_q[j] = acc;
        asm volatile("bar.sync 2, 256;" ::: "memory");

        // p[v] = emb[v] . q   (8 B-warps x 8 vids)
        #pragma unroll
        for (int rr = 0; rr < 8; ++rr) {
            const int v = (wid - 8) * 8 + rr;
            const float* er = emb + v * HID;
            float a2 = 0.f;
            #pragma unroll
            for (int k = 0; k < 8; ++k)
                a2 += er[lane + 32 * k] * s_q[lane + 32 * k];
            #pragma unroll
            for (int off = 16; off > 0; off >>= 1)
                a2 += __shfl_xor_sync(0xffffffffu, a2, off);
            if (lane == 0) s_pv[v] = a2;
        }
    }
    __syncthreads();

    const int m = s_m;
    const int ne = (m > FAST) ? (m - FAST) : 0;
    const int k1 = ne;
    const int k2 = (ne > SLOW) ? (ne - SLOW) : 0;
    const int mrank = s_mrank;

    if (tid < VOCAB) {
        int h1 = s_ha[tid] - (tid == mrank ? 1 : 0);
        s_h1[tid] = h1;
        s_h2[tid] = h1 - s_ht[tid];
    }
    __syncthreads();

    if (wid == 0) {
        int a1_ = s_h1[2 * lane], b1_ = s_h1[2 * lane + 1];
        int a2_ = s_h2[2 * lane], b2_ = s_h2[2 * lane + 1];
        int s1 = warp_incl_scan(a1_ + b1_, lane);
        int s2 = warp_incl_scan(a2_ + b2_, lane);
        int e1 = s1 - a1_ - b1_;
        int e2 = s2 - a2_ - b2_;
        s_c1[2 * lane] = e1;  s_c1[2 * lane + 1] = e1 + a1_;
        s_c2[2 * lane] = e2;  s_c2[2 * lane + 1] = e2 + a2_;
    }
    __syncthreads();

    int ct = 0;
    float p = 0.f;
    if (tid < VOCAB) {
        const int h1 = s_h1[tid], h2 = s_h2[tid];
        int e1 = k1 - s_c1[tid]; e1 = e1 < 0 ? 0 : e1; e1 = e1 > h1 ? h1 : e1;
        int e2 = k2 - s_c2[tid]; e2 = e2 < 0 ? 0 : e2; e2 = e2 > h2 ? h2 : e2;
        ct = (h1 - e1 + (tid == mrank ? 1 : 0)) + (e1 - e2);
        p = s_pv[s_vid[tid]];
    }

    // softmax over 64 ranks (warps 0-1)
    if (wid < 2) {
        float v = (ct > 0) ? p : -3.402823466e38f;
        #pragma unroll
        for (int off = 16; off > 0; off >>= 1)
            v = fmaxf(v, __shfl_xor_sync(0xffffffffu, v, off));
        if (lane == 0) s_r8[wid] = v;
    }
    __syncthreads();
    const float mx = fmaxf(s_r8[0], s_r8[1]);
    __syncthreads();
    float e = 0.f;
    if (wid < 2) {
        e = (ct > 0) ? (float)ct * expf(p - mx) : 0.f;
        float sm = e;
        #pragma unroll
        for (int off = 16; off > 0; off >>= 1)
            sm += __shfl_xor_sync(0xffffffffu, sm, off);
        if (lane == 0) s_r8[wid] = sm;
    }
    __syncthreads();
    const float tot = s_r8[0] + s_r8[1];
    const float inv = (tot > 0.f) ? (1.f / tot) : 0.f;
    if (tid < VOCAB) s_w[tid] = e * inv;
    __syncthreads();

    // ctx: 512 threads, each h handled by 2 threads (32 r's each)
    {
        const int h = tid & 255;
        const int half = tid >> 8;
        float c = 0.f;
        #pragma unroll 8
        for (int rr = 0; rr < 32; ++rr) {
            const int r = half * 32 + rr;
            c += s_w[r] * emb[s_vid[r] * HID + h];
        }
        s_ctxp[tid] = c;
    }
    __syncthreads();
    if (tid < HID) s_ctx[tid] = s_ctxp[tid] + s_ctxp[tid + 256];
    __syncthreads();

    // logits: 512 threads, 8 h-slices x 64 j
    {
        const int j = tid & 63;
        const int oct = tid >> 6;
        float acc = 0.f;
        #pragma unroll 8
        for (int k = 0; k < 32; ++k) {
            const int h = oct * 32 + k;
            acc += s_ctx[h] * Wo[h * VOCAB + j];
        }
        s_half[tid] = acc;
    }
    __syncthreads();
    if (tid < VOCAB) {
        float acc = bo[tid];
        #pragma unroll
        for (int o = 0; o < 8; ++o) acc += s_half[o * 64 + tid];
        out[b * VOCAB + tid] = acc;
    }
}

extern "C" void kernel_launch(void* const* d_in, const int* in_sizes, int n_in,
                              void* d_out, int out_size) {
    const int*   seq = (const int*)d_in[0];
    const float* emb = (const float*)d_in[1];
    const float* Wg  = (const float*)d_in[2];
    const float* bg  = (const float*)d_in[3];
    const float* Wd  = (const float*)d_in[4];
    const float* bd  = (const float*)d_in[5];
    const float* Wq  = (const float*)d_in[6];
    const float* bq  = (const float*)d_in[7];
    const float* Wo  = (const float*)d_in[8];
    const float* bo  = (const float*)d_in[9];
    float* out = (float*)d_out;

    fused_kernel<<<BATCH, 512>>>(seq, emb, Wg, bg, Wd, bd, Wq, bq, Wo, bo, out);
}